// round 1
// baseline (speedup 1.0000x reference)
#include <cuda_runtime.h>

// Shapes (fixed for this problem)
#define NROWS 256        // batch N
#define DOUT 256         // backbone output dim
#define KDIM 180000      // I*C*T*V*M
#define RSPACE 60000     // 4 coordinate-triples * 15000 positions
#define SPLITS 75        // split-K factor (7500 k-tiles / 100 per CTA)
#define TILES_PER_CTA 100
#define KT 8             // r-positions per k-tile (each expands to 3 K columns)

// Scratch (static __device__ allocations are the sanctioned mechanism)
__device__ float g_Rtot[9];
__device__ float g_partials[SPLITS * NROWS * DOUT];   // ~19.7 MB

// ---------------------------------------------------------------------------
// Kernel 0: Rtot = (R_rotate*rw) @ (R_shear*sw) @ (R_scale*cw)   (elementwise
// gating, then 3x3 matrix products). Single thread; trivial.
// ---------------------------------------------------------------------------
__global__ void rtot_kernel(const float* __restrict__ rw,
                            const float* __restrict__ sw,
                            const float* __restrict__ cw,
                            const float* __restrict__ Rr_,
                            const float* __restrict__ Rs_,
                            const float* __restrict__ Rc_) {
    float Rr[9], Rs[9], Rc[9], T[9];
    for (int i = 0; i < 9; i++) {
        Rr[i] = Rr_[i] * rw[i];
        Rs[i] = Rs_[i] * sw[i];
        Rc[i] = Rc_[i] * cw[i];
    }
    for (int i = 0; i < 3; i++)
        for (int j = 0; j < 3; j++) {
            float s = 0.f;
            for (int k = 0; k < 3; k++) s += Rr[i*3+k] * Rs[k*3+j];
            T[i*3+j] = s;
        }
    for (int i = 0; i < 3; i++)
        for (int j = 0; j < 3; j++) {
            float s = 0.f;
            for (int k = 0; k < 3; k++) s += T[i*3+k] * Rc[k*3+j];
            g_Rtot[i*3+j] = s;
        }
}

// ---------------------------------------------------------------------------
// Kernel 1: fused augmentation + GEMM (split-K, deterministic partials).
//
// K index k = g*15000 + r, g in [0,12): g = h*3 + d (h = i*2+chunk, d = coord).
// A[n, (h*3+d)*15000 + r] = sum_c x[n, (h*3+c)*15000 + r] * Rtot[c][d]
// We iterate over r-tiles (KT=8, 8 | 15000 so a tile never crosses a triple
// boundary), load the 3 source coordinate slices of x once, mix into 3 A
// sub-tiles, and pair them with the 3 matching W row-blocks. x and W are read
// exactly once per 128x128 output tile (2x amplification from 2x2 tiling).
//
// Grid: (2, 2, SPLITS); block 256 threads; 8x8 register micro-tiles.
// ---------------------------------------------------------------------------
__global__ __launch_bounds__(256, 2)
void gemm_kernel(const float* __restrict__ x, const float* __restrict__ W) {
    __shared__ __align__(16) float As[3*KT][132];  // [c*8+kt][m], pad 132 -> conflict-free
    __shared__ __align__(16) float Bs[3*KT][128];  // [c*8+kt][n]

    const int bx = blockIdx.x, by = blockIdx.y, s = blockIdx.z;
    const int m0 = by * 128, n0 = bx * 128;
    const int tid = threadIdx.x;
    const int tx = tid & 15, ty = tid >> 4;   // 16x16 thread grid

    const float R00 = g_Rtot[0], R01 = g_Rtot[1], R02 = g_Rtot[2];
    const float R10 = g_Rtot[3], R11 = g_Rtot[4], R12 = g_Rtot[5];
    const float R20 = g_Rtot[6], R21 = g_Rtot[7], R22 = g_Rtot[8];

    float acc[8][8];
    #pragma unroll
    for (int i = 0; i < 8; i++)
        #pragma unroll
        for (int j = 0; j < 8; j++) acc[i][j] = 0.f;

    for (int t = 0; t < TILES_PER_CTA; t++) {
        const int r    = (s * TILES_PER_CTA + t) * KT;   // < 60000, 8-aligned
        const int trip = r / 15000;                      // which coordinate triple
        const int rr   = r - trip * 15000;
        const int kbase = trip * 45000 + rr;             // K index of coord 0

        // ---- A tiles: load 3 x-slices, mix via Rtot. 1024 (kt,row) pairs.
        #pragma unroll
        for (int it = 0; it < 4; it++) {
            const int p   = tid + it * 256;
            const int kt  = p & 7;
            const int row = p >> 3;
            const float* xp = x + (long)(m0 + row) * KDIM + kbase + kt;
            const float x0 = xp[0];
            const float x1 = xp[15000];
            const float x2 = xp[30000];
            As[       kt][row] = x0 * R00 + x1 * R10 + x2 * R20;
            As[  KT + kt][row] = x0 * R01 + x1 * R11 + x2 * R21;
            As[2*KT + kt][row] = x0 * R02 + x1 * R12 + x2 * R22;
        }
        // ---- B tiles: 24 W rows x 128 cols, float4 (768 vec loads)
        #pragma unroll
        for (int it = 0; it < 3; it++) {
            const int q    = tid + it * 256;
            const int col4 = q & 31;
            const int krow = q >> 5;          // 0..23 = c*8 + kt
            const int c    = krow >> 3;
            const int kt   = krow & 7;
            const float4 w4 = *(const float4*)(W + (long)(kbase + c*15000 + kt) * DOUT
                                                 + n0 + col4 * 4);
            *(float4*)&Bs[krow][col4 * 4] = w4;
        }
        __syncthreads();

        #pragma unroll 8
        for (int kk = 0; kk < 3*KT; kk++) {
            float a[8], b[8];
            *(float4*)&a[0] = *(const float4*)&As[kk][ty * 8];
            *(float4*)&a[4] = *(const float4*)&As[kk][ty * 8 + 4];
            *(float4*)&b[0] = *(const float4*)&Bs[kk][tx * 8];
            *(float4*)&b[4] = *(const float4*)&Bs[kk][tx * 8 + 4];
            #pragma unroll
            for (int i = 0; i < 8; i++)
                #pragma unroll
                for (int j = 0; j < 8; j++)
                    acc[i][j] += a[i] * b[j];
        }
        __syncthreads();
    }

    // partials[s][m][n]
    float* pb = g_partials + ((long)s * NROWS + m0 + ty * 8) * DOUT + n0 + tx * 8;
    #pragma unroll
    for (int i = 0; i < 8; i++) {
        *(float4*)&pb[i * DOUT + 0] = make_float4(acc[i][0], acc[i][1], acc[i][2], acc[i][3]);
        *(float4*)&pb[i * DOUT + 4] = make_float4(acc[i][4], acc[i][5], acc[i][6], acc[i][7]);
    }
}

// ---------------------------------------------------------------------------
// Kernel 2: reduce split-K partials + bias, write z into both output slots.
// out layout: [0]=loss_mean, [1 .. 65536]=z, [65537 .. 131072]=z (again).
// ---------------------------------------------------------------------------
__global__ void reduce_kernel(const float* __restrict__ b,
                              float* __restrict__ out, int out_size) {
    const int m = blockIdx.x;
    const int n = threadIdx.x;
    float sum = b[n];
    #pragma unroll 5
    for (int s = 0; s < SPLITS; s++)
        sum += g_partials[((long)s * NROWS + m) * DOUT + n];
    const int idx = m * DOUT + n;
    if (1 + idx < out_size)                 out[1 + idx] = sum;
    if (1 + NROWS*DOUT + idx < out_size)    out[1 + NROWS*DOUT + idx] = sum;
}

// ---------------------------------------------------------------------------
// Kernel 3: loss. With q = z and z_d = z:
//   zn_i = z_i / ||z_i||;  sim = zn zn^T;  diag_i = 1 (numerically ~1)
//   rowsum_i = inv_i * (z_i . t)  where  t = sum_j inv_j z_j   (256-vector!)
//   loss_i = 2 * (diag_i - (rowsum_i - diag_i)/255);  out[0] = mean_i loss_i
// Single CTA of 256 threads; all data ~256 KB, L2-resident.
// ---------------------------------------------------------------------------
__global__ void loss_kernel(float* __restrict__ out) {
    __shared__ float inv[256];
    __shared__ float tvec[256];
    __shared__ float red[256];
    const float* z = out + 1;
    const int i = threadIdx.x;

    // row norms
    float ss = 0.f;
    #pragma unroll 8
    for (int k = 0; k < 256; k++) {
        const float v = z[i * 256 + k];
        ss += v * v;
    }
    const float invi = rsqrtf(ss);
    inv[i] = invi;
    __syncthreads();

    // t[k] = sum_j inv[j] * z[j][k]   (thread i owns column k=i; coalesced)
    float tv = 0.f;
    #pragma unroll 8
    for (int j = 0; j < 256; j++) tv += inv[j] * z[j * 256 + i];
    tvec[i] = tv;
    __syncthreads();

    // rowsum_i and per-row loss
    float d = 0.f;
    #pragma unroll 8
    for (int k = 0; k < 256; k++) d += z[i * 256 + k] * tvec[k];
    const float rowsum = invi * d;
    const float diag   = ss * invi * invi;           // ~= 1, match reference numerics
    red[i] = 2.f * (diag - (rowsum - diag) / 255.f);
    __syncthreads();

    for (int s2 = 128; s2 > 0; s2 >>= 1) {
        if (i < s2) red[i] += red[i + s2];
        __syncthreads();
    }
    if (i == 0) out[0] = red[0] / 256.f;
}

// ---------------------------------------------------------------------------
// Inputs (metadata order): x, rotate_weight, shear_weight, scale_weight,
// W_backbone, b_backbone, R_rotate, R_shear, R_scale. Output: float32.
// ---------------------------------------------------------------------------
extern "C" void kernel_launch(void* const* d_in, const int* in_sizes, int n_in,
                              void* d_out, int out_size) {
    const float* x  = (const float*)d_in[0];
    const float* rw = (const float*)d_in[1];
    const float* sw = (const float*)d_in[2];
    const float* cw = (const float*)d_in[3];
    const float* W  = (const float*)d_in[4];
    const float* b  = (const float*)d_in[5];
    const float* Rr = (const float*)d_in[6];
    const float* Rs = (const float*)d_in[7];
    const float* Rc = (const float*)d_in[8];
    float* out = (float*)d_out;

    rtot_kernel<<<1, 1>>>(rw, sw, cw, Rr, Rs, Rc);

    dim3 grid(2, 2, SPLITS);
    gemm_kernel<<<grid, 256>>>(x, W);

    reduce_kernel<<<NROWS, DOUT>>>(b, out, out_size);
    loss_kernel<<<1, 256>>>(out);
}

// round 2
// speedup vs baseline: 2.1166x; 2.1166x over previous
#include <cuda_runtime.h>

// Shapes (fixed for this problem)
#define NROWS 256        // batch N
#define DOUT 256         // backbone output dim
#define KDIM 180000      // I*C*T*V*M
#define RSPACE 60000     // 4 coordinate-triples * 15000 positions
#define SPLITS 75        // split-K factor
#define TILES_PER_CTA 100
#define KT 8             // r-positions per k-tile (expands to 24 K columns)

// Scratch (static __device__ allocations are the sanctioned mechanism)
__device__ float g_Rtot[9];
__device__ float g_partials[SPLITS * NROWS * DOUT];   // ~19.7 MB
__device__ float g_inv[NROWS];
__device__ float g_diag[NROWS];
__device__ float g_t[DOUT];
__device__ float g_rowloss[NROWS];

// ---------------------------------------------------------------------------
// fp32 -> tf32 (round-to-nearest) kept as raw bits for mma operands
// ---------------------------------------------------------------------------
__device__ __forceinline__ unsigned f2tf32(float f) {
    unsigned u;
    asm("cvt.rna.tf32.f32 %0, %1;" : "=r"(u) : "f"(f));
    return u;
}

__device__ __forceinline__ void mma_tf32(float* d, const unsigned* a, const unsigned* b) {
    asm volatile(
        "mma.sync.aligned.m16n8k8.row.col.f32.tf32.tf32.f32 "
        "{%0,%1,%2,%3}, {%4,%5,%6,%7}, {%8,%9}, {%0,%1,%2,%3};\n"
        : "+f"(d[0]), "+f"(d[1]), "+f"(d[2]), "+f"(d[3])
        : "r"(a[0]), "r"(a[1]), "r"(a[2]), "r"(a[3]),
          "r"(b[0]), "r"(b[1]));
}

// ---------------------------------------------------------------------------
// Kernel 0: Rtot = (R_rotate*rw) @ (R_shear*sw) @ (R_scale*cw)
// ---------------------------------------------------------------------------
__global__ void rtot_kernel(const float* __restrict__ rw,
                            const float* __restrict__ sw,
                            const float* __restrict__ cw,
                            const float* __restrict__ Rr_,
                            const float* __restrict__ Rs_,
                            const float* __restrict__ Rc_) {
    float Rr[9], Rs[9], Rc[9], T[9];
    for (int i = 0; i < 9; i++) {
        Rr[i] = Rr_[i] * rw[i];
        Rs[i] = Rs_[i] * sw[i];
        Rc[i] = Rc_[i] * cw[i];
    }
    for (int i = 0; i < 3; i++)
        for (int j = 0; j < 3; j++) {
            float s = 0.f;
            for (int k = 0; k < 3; k++) s += Rr[i*3+k] * Rs[k*3+j];
            T[i*3+j] = s;
        }
    for (int i = 0; i < 3; i++)
        for (int j = 0; j < 3; j++) {
            float s = 0.f;
            for (int k = 0; k < 3; k++) s += T[i*3+k] * Rc[k*3+j];
            g_Rtot[i*3+j] = s;
        }
}

// ---------------------------------------------------------------------------
// Kernel 1: fused augmentation + GEMM on tensor cores (tf32 mma.sync).
// Grid (2,2,SPLITS), block 256 = 8 warps, each warp owns a 64x32 sub-tile
// (4x4 grid of m16n8k8 mma tiles). Split-K partials are deterministic.
// ---------------------------------------------------------------------------
__global__ __launch_bounds__(256, 2)
void gemm_kernel(const float* __restrict__ x, const float* __restrict__ W) {
    // As[m][k]: 128 x 24 tf32, row stride 25 (pad). Bs[k][n]: 24 x 128, stride 132.
    __shared__ __align__(16) unsigned As[128 * 25];
    __shared__ __align__(16) unsigned Bs[24 * 132];

    const int bx = blockIdx.x, by = blockIdx.y, s = blockIdx.z;
    const int m0 = by * 128, n0 = bx * 128;
    const int tid  = threadIdx.x;
    const int lane = tid & 31, warp = tid >> 5;
    const int g = lane >> 2, t = lane & 3;     // groupID / thread-in-group
    const int wm = warp & 1, wn = warp >> 1;   // 2 x 4 warp grid
    const int mw = wm * 64, nw = wn * 32;

    const float R00 = g_Rtot[0], R01 = g_Rtot[1], R02 = g_Rtot[2];
    const float R10 = g_Rtot[3], R11 = g_Rtot[4], R12 = g_Rtot[5];
    const float R20 = g_Rtot[6], R21 = g_Rtot[7], R22 = g_Rtot[8];

    float acc[4][4][4];
    #pragma unroll
    for (int mi = 0; mi < 4; mi++)
        #pragma unroll
        for (int ni = 0; ni < 4; ni++)
            #pragma unroll
            for (int r = 0; r < 4; r++) acc[mi][ni][r] = 0.f;

    for (int tile = 0; tile < TILES_PER_CTA; tile++) {
        const int r    = (s * TILES_PER_CTA + tile) * KT;  // < 60000, 8-aligned
        const int trip = r / 15000;
        const int rr   = r - trip * 15000;
        const int kbase = trip * 45000 + rr;               // K index of coord 0

        // ---- A: load 3 x-slices, mix via Rtot, store tf32. 1024 (kt,row) pairs.
        #pragma unroll
        for (int it = 0; it < 4; it++) {
            const int p   = tid + it * 256;
            const int kt  = p & 7;
            const int row = p >> 3;
            const float* xp = x + (long)(m0 + row) * KDIM + kbase + kt;
            const float x0 = xp[0];
            const float x1 = xp[15000];
            const float x2 = xp[30000];
            As[row * 25 +      kt] = f2tf32(x0 * R00 + x1 * R10 + x2 * R20);
            As[row * 25 +  8 + kt] = f2tf32(x0 * R01 + x1 * R11 + x2 * R21);
            As[row * 25 + 16 + kt] = f2tf32(x0 * R02 + x1 * R12 + x2 * R22);
        }
        // ---- B: 24 W rows x 128 cols, float4 loads -> tf32
        #pragma unroll
        for (int it = 0; it < 3; it++) {
            const int q    = tid + it * 256;
            const int col4 = q & 31;
            const int krow = q >> 5;          // 0..23 = d*8 + kt
            const int d    = krow >> 3;
            const int kt   = krow & 7;
            const float4 w4 = *(const float4*)(W + (long)(kbase + d * 15000 + kt) * DOUT
                                                 + n0 + col4 * 4);
            unsigned* bp = &Bs[krow * 132 + col4 * 4];
            bp[0] = f2tf32(w4.x); bp[1] = f2tf32(w4.y);
            bp[2] = f2tf32(w4.z); bp[3] = f2tf32(w4.w);
        }
        __syncthreads();

        // ---- 3 k-steps of m16n8k8 over the 24-wide k-tile
        #pragma unroll
        for (int ks = 0; ks < 3; ks++) {
            const int ko = ks * 8;
            unsigned a[4][4], b[4][2];
            #pragma unroll
            for (int mi = 0; mi < 4; mi++) {
                const int base = (mw + mi * 16 + g) * 25 + ko + t;
                a[mi][0] = As[base];
                a[mi][1] = As[base + 8 * 25];
                a[mi][2] = As[base + 4];
                a[mi][3] = As[base + 8 * 25 + 4];
            }
            #pragma unroll
            for (int ni = 0; ni < 4; ni++) {
                const int bidx = (ko + t) * 132 + nw + ni * 8 + g;
                b[ni][0] = Bs[bidx];
                b[ni][1] = Bs[bidx + 4 * 132];
            }
            #pragma unroll
            for (int mi = 0; mi < 4; mi++)
                #pragma unroll
                for (int ni = 0; ni < 4; ni++)
                    mma_tf32(acc[mi][ni], a[mi], b[ni]);
        }
        __syncthreads();
    }

    // ---- epilogue: write split-K partials
    #pragma unroll
    for (int mi = 0; mi < 4; mi++) {
        #pragma unroll
        for (int ni = 0; ni < 4; ni++) {
            const int row = m0 + mw + mi * 16 + g;
            const int col = n0 + nw + ni * 8 + 2 * t;
            float* p = g_partials + ((long)s * NROWS + row) * DOUT + col;
            *(float2*)p              = make_float2(acc[mi][ni][0], acc[mi][ni][1]);
            *(float2*)(p + 8 * DOUT) = make_float2(acc[mi][ni][2], acc[mi][ni][3]);
        }
    }
}

// ---------------------------------------------------------------------------
// Kernel 2: reduce split-K partials + bias -> z (both output slots).
// Also computes per-row inv-norm and diag (fused, saves a kernel).
// ---------------------------------------------------------------------------
__global__ void reduce_kernel(const float* __restrict__ b,
                              float* __restrict__ out, int out_size) {
    __shared__ float red[256];
    const int m = blockIdx.x;
    const int n = threadIdx.x;
    float sum = b[n];
    #pragma unroll 5
    for (int s = 0; s < SPLITS; s++)
        sum += g_partials[((long)s * NROWS + m) * DOUT + n];
    const int idx = m * DOUT + n;
    if (1 + idx < out_size)                 out[1 + idx] = sum;
    if (1 + NROWS * DOUT + idx < out_size)  out[1 + NROWS * DOUT + idx] = sum;

    red[n] = sum * sum;
    __syncthreads();
    for (int s2 = 128; s2 > 0; s2 >>= 1) {
        if (n < s2) red[n] += red[n + s2];
        __syncthreads();
    }
    if (n == 0) {
        const float ss  = red[0];
        const float inv = rsqrtf(ss);
        g_inv[m]  = inv;
        g_diag[m] = ss * inv * inv;   // ~= 1, matches reference numerics
    }
}

// ---------------------------------------------------------------------------
// Kernel 3: t[k] = sum_j inv[j] * z[j][k]  (1024 threads: 4-way j-parallel)
// ---------------------------------------------------------------------------
__global__ void tvec_kernel(const float* __restrict__ out) {
    __shared__ float tp[4][256];
    const float* z = out + 1;
    const int k  = threadIdx.x & 255;
    const int jj = threadIdx.x >> 8;   // 0..3
    float tv = 0.f;
    #pragma unroll 8
    for (int j = jj * 64; j < (jj + 1) * 64; j++)
        tv += g_inv[j] * z[j * 256 + k];
    tp[jj][k] = tv;
    __syncthreads();
    if (jj == 0)
        g_t[k] = tp[0][k] + tp[1][k] + tp[2][k] + tp[3][k];
}

// ---------------------------------------------------------------------------
// Kernel 4: per-row loss_i = 2*(diag_i - (inv_i*(z_i . t) - diag_i)/255)
// ---------------------------------------------------------------------------
__global__ void rowloss_kernel(const float* __restrict__ out) {
    __shared__ float red[256];
    const float* z = out + 1;
    const int i = blockIdx.x;
    const int k = threadIdx.x;
    red[k] = z[i * 256 + k] * g_t[k];
    __syncthreads();
    for (int s2 = 128; s2 > 0; s2 >>= 1) {
        if (k < s2) red[k] += red[k + s2];
        __syncthreads();
    }
    if (k == 0) {
        const float rowsum = g_inv[i] * red[0];
        const float diag   = g_diag[i];
        g_rowloss[i] = 2.f * (diag - (rowsum - diag) / 255.f);
    }
}

// ---------------------------------------------------------------------------
// Kernel 5: mean of per-row losses -> out[0]
// ---------------------------------------------------------------------------
__global__ void mean_kernel(float* __restrict__ out) {
    __shared__ float red[256];
    const int i = threadIdx.x;
    red[i] = g_rowloss[i];
    __syncthreads();
    for (int s2 = 128; s2 > 0; s2 >>= 1) {
        if (i < s2) red[i] += red[i + s2];
        __syncthreads();
    }
    if (i == 0) out[0] = red[0] / 256.f;
}

// ---------------------------------------------------------------------------
// Inputs (metadata order): x, rotate_weight, shear_weight, scale_weight,
// W_backbone, b_backbone, R_rotate, R_shear, R_scale. Output: float32.
// ---------------------------------------------------------------------------
extern "C" void kernel_launch(void* const* d_in, const int* in_sizes, int n_in,
                              void* d_out, int out_size) {
    const float* x  = (const float*)d_in[0];
    const float* rw = (const float*)d_in[1];
    const float* sw = (const float*)d_in[2];
    const float* cw = (const float*)d_in[3];
    const float* W  = (const float*)d_in[4];
    const float* b  = (const float*)d_in[5];
    const float* Rr = (const float*)d_in[6];
    const float* Rs = (const float*)d_in[7];
    const float* Rc = (const float*)d_in[8];
    float* out = (float*)d_out;

    rtot_kernel<<<1, 1>>>(rw, sw, cw, Rr, Rs, Rc);

    dim3 grid(2, 2, SPLITS);
    gemm_kernel<<<grid, 256>>>(x, W);

    reduce_kernel<<<NROWS, DOUT>>>(b, out, out_size);
    tvec_kernel<<<1, 1024>>>(out);
    rowloss_kernel<<<NROWS, 256>>>(out);
    mean_kernel<<<1, 256>>>(out);
}